// round 13
// baseline (speedup 1.0000x reference)
#include <cuda_runtime.h>

typedef unsigned long long u64;

#define NQ   14
#define DIM  (1 << NQ)       // 16384
#define NL   3
#define TPB  512
#define AMPS 32              // DIM / TPB
#define SMEM_BYTES (DIM * sizeof(u64))   // 131072

// ---- packed f32x2 helpers (B300: fma.rn.f32x2 only reachable via PTX) ----
__device__ __forceinline__ u64 pack2(float lo, float hi) {
    u64 r; asm("mov.b64 %0, {%1,%2};" : "=l"(r) : "f"(lo), "f"(hi)); return r;
}
__device__ __forceinline__ void unpack2(u64 a, float& lo, float& hi) {
    asm("mov.b64 {%0,%1}, %2;" : "=f"(lo), "=f"(hi) : "l"(a));
}
__device__ __forceinline__ u64 swap64(u64 a) {
    u64 r;
    asm("{\n\t.reg .b32 lo,hi;\n\tmov.b64 {lo,hi}, %1;\n\tmov.b64 %0, {hi,lo};\n\t}"
        : "=l"(r) : "l"(a));
    return r;
}
__device__ __forceinline__ u64 fma2(u64 a, u64 b, u64 c) {
    u64 d; asm("fma.rn.f32x2 %0, %1, %2, %3;" : "=l"(d) : "l"(a), "l"(b), "l"(c)); return d;
}
__device__ __forceinline__ u64 mul2(u64 a, u64 b) {
    u64 d; asm("mul.rn.f32x2 %0, %1, %2;" : "=l"(d) : "l"(a), "l"(b)); return d;
}

// packed complex 2x2 apply: g = 8 packed consts
//   g[0]=(r00,r00) g[1]=(-i00,i00) g[2]=(r01,r01) g[3]=(-i01,i01)
//   g[4]=(r10,r10) g[5]=(-i10,i10) g[6]=(r11,r11) g[7]=(-i11,i11)
__device__ __forceinline__ void apply2p(const u64* g, u64& a0, u64& a1) {
    u64 s0 = swap64(a0), s1 = swap64(a1);
    u64 n0 = mul2(s1, g[3]);
    n0 = fma2(a1, g[2], n0);
    n0 = fma2(s0, g[1], n0);
    n0 = fma2(a0, g[0], n0);
    u64 n1 = mul2(s1, g[7]);
    n1 = fma2(a1, g[6], n1);
    n1 = fma2(s0, g[5], n1);
    n1 = fma2(a0, g[4], n1);
    a0 = n0; a1 = n1;
}

// bank-conflict-avoiding SMEM swizzle (pure relabeling; used on EVERY s[] access)
__device__ __forceinline__ unsigned swz(unsigned a) { return a ^ ((a >> 5) & 31u); }

__global__ __launch_bounds__(TPB, 1)
void qsim_kernel(const float* __restrict__ x,
                 const float* __restrict__ qw,
                 const float* __restrict__ wlin,
                 const float* __restrict__ blin,
                 float* __restrict__ out)
{
    extern __shared__ u64 s[];                // 128 KB exchange buffer (packed amps)
    __shared__ u64   sg[NL * NQ][8];          // packed Rot gate constants
    __shared__ float red[TPB / 32];

    const int t    = threadIdx.x;
    const int lane = t & 31;
    const int b    = blockIdx.x;

    u64 r[AMPS];                              // this thread's 32 packed amplitudes

    // ---- cooperative gate precompute + pack: one thread per (layer,wire) ----
    if (t < NL * NQ) {
        float phi = qw[t * 3 + 0], th = qw[t * 3 + 1], om = qw[t * 3 + 2];
        float ct, st, ca, sa, cb, sb;
        sincosf(0.5f * th,         &st, &ct);
        sincosf(0.5f * (phi + om), &sa, &ca);
        sincosf(0.5f * (phi - om), &sb, &cb);
        float r00 =  ct * ca, i00 = -ct * sa;
        float r01 = -st * cb, i01 = -st * sb;
        float r10 =  st * cb, i10 = -st * sb;
        float r11 =  ct * ca, i11 =  ct * sa;
        sg[t][0] = pack2(r00, r00);  sg[t][1] = pack2(-i00, i00);
        sg[t][2] = pack2(r01, r01);  sg[t][3] = pack2(-i01, i01);
        sg[t][4] = pack2(r10, r10);  sg[t][5] = pack2(-i10, i10);
        sg[t][6] = pack2(r11, r11);  sg[t][7] = pack2(-i11, i11);
    }

    // ---- init in registers: RX product state on |0..0> ----
    // Phase-A mapping: logical index y = (t<<5) | u  (u = register index, bits 0-4)
    // y bit (5+j) = t bit j  -> wire 8-j ;  y bit q (q<5) -> wire 13-q
    float tmag = 1.0f;
    #pragma unroll
    for (int j = 0; j < 9; j++) {
        float sv, cv;
        sincosf(0.5f * x[b * NQ + (8 - j)], &sv, &cv);
        tmag *= ((t >> j) & 1) ? sv : cv;
    }
    float su[5], cu[5];
    #pragma unroll
    for (int q = 0; q < 5; q++)
        sincosf(0.5f * x[b * NQ + (13 - q)], &su[q], &cu[q]);
    const int tp = __popc((unsigned)t);
    #pragma unroll
    for (int u = 0; u < AMPS; u++) {
        float m = tmag;
        #pragma unroll
        for (int q = 0; q < 5; q++)
            m *= ((u >> q) & 1) ? su[q] : cu[q];
        int k = (tp + __popc((unsigned)u)) & 3;      // (-i)^popc(y)
        float re = (k == 0) ? m : ((k == 2) ? -m : 0.0f);
        float im = (k == 3) ? m : ((k == 1) ? -m : 0.0f);
        r[u] = pack2(re, im);
    }
    __syncthreads();                                 // sg[] ready

    for (int l = 0; l < NL; l++) {
        // ---- Phase A load (layers 1,2): gather with previous ring folded in ----
        // psi_new[y] = psi_old[F(y)],  F = ring map built by ops w=13..0 (descending);
        // its inverse (ascending build) is the numerically-validated sign-fold matrix.
        if (l > 0) {
            const int rr = l;                        // previous layer's ring range
            unsigned Fcol[NQ];
            #pragma unroll
            for (int j = 0; j < NQ; j++) {
                unsigned z = 1u << j;
                for (int w = NQ - 1; w >= 0; w--) {
                    int bc = NQ - 1 - w;
                    int bt = NQ - 1 - ((w + rr) % NQ);
                    z ^= ((z >> bc) & 1u) << bt;
                }
                Fcol[j] = z;
            }
            unsigned Fb = 0;
            #pragma unroll
            for (int j = 0; j < 9; j++)
                if ((t >> j) & 1) Fb ^= Fcol[5 + j];
            #pragma unroll
            for (int u = 0; u < AMPS; u++) {
                unsigned fy = Fb;
                if (u & 1)  fy ^= Fcol[0];
                if (u & 2)  fy ^= Fcol[1];
                if (u & 4)  fy ^= Fcol[2];
                if (u & 8)  fy ^= Fcol[3];
                if (u & 16) fy ^= Fcol[4];
                r[u] = s[swz(fy)];
            }
        }

        // ---- Phase A gates: wires 9-13 (register bits 0-4), wires 5-8 (lane bits 0-3) ----
        #pragma unroll
        for (int q = 0; q < 5; q++) {                // wire 13-q on register bit q
            u64 gl[8];
            #pragma unroll
            for (int e = 0; e < 8; e++) gl[e] = sg[l * NQ + (13 - q)][e];
            #pragma unroll
            for (int k = 0; k < AMPS; k++)
                if (!(k & (1 << q))) apply2p(gl, r[k], r[k | (1 << q)]);
        }
        #pragma unroll
        for (int ql = 0; ql < 4; ql++) {             // wire 8-ql on lane bit ql
            const u64* g = sg[l * NQ + (8 - ql)];
            int bit = (lane >> ql) & 1;
            u64 Pa = bit ? g[6] : g[0];
            u64 Qa = bit ? g[7] : g[1];
            u64 Pb = bit ? g[4] : g[2];
            u64 Qb = bit ? g[5] : g[3];
            #pragma unroll
            for (int k = 0; k < AMPS; k++) {
                u64 o  = __shfl_xor_sync(0xffffffffu, r[k], 1 << ql);
                u64 sk = swap64(r[k]);
                u64 so = swap64(o);
                u64 n = mul2(so, Qb);
                n = fma2(o,    Pb, n);
                n = fma2(sk,   Qa, n);
                n = fma2(r[k], Pa, n);
                r[k] = n;
            }
        }

        __syncthreads();                             // all phase-A loads done
        #pragma unroll
        for (int u = 0; u < AMPS; u++)               // store contiguous layout
            s[swz((unsigned)(t << 5) | u)] = r[u];
        __syncthreads();                             // stores visible

        // ---- Phase B: logical y = (u<<9) | t  (bits 9-13 register-local) ----
        #pragma unroll
        for (int u = 0; u < AMPS; u++)
            r[u] = s[swz(((unsigned)u << 9) | (unsigned)t)];

        #pragma unroll
        for (int q = 0; q < 5; q++) {                // wire 4-q on register bit q (y bit 9+q)
            u64 gl[8];
            #pragma unroll
            for (int e = 0; e < 8; e++) gl[e] = sg[l * NQ + (4 - q)][e];
            #pragma unroll
            for (int k = 0; k < AMPS; k++)
                if (!(k & (1 << q))) apply2p(gl, r[k], r[k | (1 << q)]);
        }

        if (l < NL - 1) {
            __syncthreads();                         // all phase-B loads done
            #pragma unroll
            for (int u = 0; u < AMPS; u++)
                s[swz(((unsigned)u << 9) | (unsigned)t)] = r[u];
            __syncthreads();                         // stores visible for next A-load
        }
    }

    // ---- last CNOT ring (r = NL) folded into expval signs (validated recurrence) ----
    unsigned Ar[NQ];
    #pragma unroll
    for (int i = 0; i < NQ; i++) Ar[i] = 1u << i;
    {
        const int rr = NL;
        #pragma unroll
        for (int w = 0; w < NQ; w++) {
            int bc = NQ - 1 - w;
            int bt = NQ - 1 - ((w + rr) % NQ);
            Ar[bt] ^= Ar[bc];
        }
    }
    float    wl[NQ];
    unsigned rf[NQ];
    #pragma unroll
    for (int w = 0; w < NQ; w++) { wl[w] = wlin[w]; rf[w] = Ar[NQ - 1 - w]; }

    float acc = 0.0f;
    #pragma unroll
    for (int u = 0; u < AMPS; u++) {
        unsigned y = ((unsigned)u << 9) | (unsigned)t;
        float ax, ay;
        unpack2(r[u], ax, ay);
        float pr = ax * ax + ay * ay;
        float z  = 0.0f;
        #pragma unroll
        for (int w = 0; w < NQ; w++)
            z += ((__popc(rf[w] & y) & 1) ? -wl[w] : wl[w]);
        acc += pr * z;
    }
    #pragma unroll
    for (int off = 16; off; off >>= 1)
        acc += __shfl_down_sync(0xffffffffu, acc, off);
    if (lane == 0) red[t >> 5] = acc;
    __syncthreads();
    if (t == 0) {
        float tot = 0.0f;
        #pragma unroll
        for (int q = 0; q < TPB / 32; q++) tot += red[q];
        out[b] = tot + blin[0];
    }
}

extern "C" void kernel_launch(void* const* d_in, const int* in_sizes, int n_in,
                              void* d_out, int out_size)
{
    // Bind inputs by element count (robust to metadata ordering):
    //   x: 128*14 = 1792, q_weights: 3*14*3 = 126, w_lin: 14, b_lin: 1
    const float* x    = nullptr;
    const float* qw   = nullptr;
    const float* wlin = nullptr;
    const float* blin = nullptr;
    for (int i = 0; i < n_in; i++) {
        switch (in_sizes[i]) {
            case 1792: x    = (const float*)d_in[i]; break;
            case 126:  qw   = (const float*)d_in[i]; break;
            case 14:   wlin = (const float*)d_in[i]; break;
            case 1:    blin = (const float*)d_in[i]; break;
            default: break;
        }
    }
    float* out = (float*)d_out;                  // (128, 1)

    cudaFuncSetAttribute(qsim_kernel,
                         cudaFuncAttributeMaxDynamicSharedMemorySize,
                         SMEM_BYTES);

    qsim_kernel<<<128, TPB, SMEM_BYTES>>>(x, qw, wlin, blin, out);
}

// round 16
// speedup vs baseline: 1.0452x; 1.0452x over previous
#include <cuda_runtime.h>

typedef unsigned long long u64;

#define NQ   14
#define DIM  (1 << NQ)       // 16384
#define NL   3
#define TPB  512
#define HALF 16              // packed units per thread (32 amps / 2)
#define SMEM_BYTES (DIM * sizeof(float2))   // 131072

// ---- packed f32x2 helpers ----
__device__ __forceinline__ u64 pack2(float lo, float hi) {
    u64 r; asm("mov.b64 %0, {%1,%2};" : "=l"(r) : "f"(lo), "f"(hi)); return r;
}
__device__ __forceinline__ void unpack2(u64 a, float& lo, float& hi) {
    asm("mov.b64 {%0,%1}, %2;" : "=f"(lo), "=f"(hi) : "l"(a));
}
__device__ __forceinline__ u64 blo(u64 a) {   // (lo,lo)
    u64 r; asm("{\n\t.reg .b32 l,h;\n\tmov.b64 {l,h}, %1;\n\tmov.b64 %0, {l,l};\n\t}"
               : "=l"(r) : "l"(a)); return r;
}
__device__ __forceinline__ u64 bhi(u64 a) {   // (hi,hi)
    u64 r; asm("{\n\t.reg .b32 l,h;\n\tmov.b64 {l,h}, %1;\n\tmov.b64 %0, {h,h};\n\t}"
               : "=l"(r) : "l"(a)); return r;
}
__device__ __forceinline__ u64 fma2(u64 a, u64 b, u64 c) {
    u64 d; asm("fma.rn.f32x2 %0, %1, %2, %3;" : "=l"(d) : "l"(a), "l"(b), "l"(c)); return d;
}
__device__ __forceinline__ u64 mul2(u64 a, u64 b) {
    u64 d; asm("mul.rn.f32x2 %0, %1, %2;" : "=l"(d) : "l"(a), "l"(b)); return d;
}

// Vectorized complex 2x2 butterfly on SoA-packed pair (two independent problems).
// g: [0]=(r00,r00) [1]=(-i00,-i00) [2]=(r01,r01) [3]=(-i01,-i01)
//    [4]=(i00,i00) [5]=(i01,i01)   [6]=(-r01,-r01)
// Rot structure: g11 = conj(g00), g10 = -conj(g01).
__device__ __forceinline__ void apply2v(const u64* g, u64& R0, u64& I0, u64& R1, u64& I1)
{
    u64 n0r = mul2(R0, g[0]); n0r = fma2(I0, g[1], n0r); n0r = fma2(R1, g[2], n0r); n0r = fma2(I1, g[3], n0r);
    u64 n0i = mul2(R0, g[4]); n0i = fma2(I0, g[0], n0i); n0i = fma2(R1, g[5], n0i); n0i = fma2(I1, g[2], n0i);
    u64 n1r = mul2(R0, g[6]); n1r = fma2(I0, g[3], n1r); n1r = fma2(R1, g[0], n1r); n1r = fma2(I1, g[4], n1r);
    u64 n1i = mul2(R0, g[5]); n1i = fma2(I0, g[6], n1i); n1i = fma2(R1, g[1], n1i); n1i = fma2(I1, g[0], n1i);
    R0 = n0r; I0 = n0i; R1 = n1r; I1 = n1i;
}

// bank-conflict-avoiding SMEM swizzle (pure relabeling; used on EVERY s[] access)
__device__ __forceinline__ unsigned swz(unsigned a) { return a ^ ((a >> 5) & 31u); }

__global__ __launch_bounds__(TPB, 1)
void qsim_kernel(const float* __restrict__ x,
                 const float* __restrict__ qw,
                 const float* __restrict__ wlin,
                 const float* __restrict__ blin,
                 float* __restrict__ out)
{
    extern __shared__ float2 s[];             // 128 KB scalar exchange buffer
    __shared__ u64   sg[NL * NQ][14];         // packed gate constants
    __shared__ float red[TPB / 32];

    const int t    = threadIdx.x;
    const int lane = t & 31;
    const int b    = blockIdx.x;

    u64 R[HALF], I[HALF];                     // SoA packed amplitudes

    // ---- cooperative gate precompute + pack: one thread per (layer,wire) ----
    if (t < NL * NQ) {
        float phi = qw[t * 3 + 0], th = qw[t * 3 + 1], om = qw[t * 3 + 2];
        float ct, st, ca, sa, cb, sb;
        sincosf(0.5f * th,         &st, &ct);
        sincosf(0.5f * (phi + om), &sa, &ca);
        sincosf(0.5f * (phi - om), &sb, &cb);
        float r00 =  ct * ca, i00 = -ct * sa;
        float r01 = -st * cb, i01 = -st * sb;
        // uniform (vectorized / lane wires)
        sg[t][0]  = pack2(r00,  r00);
        sg[t][1]  = pack2(-i00, -i00);
        sg[t][2]  = pack2(r01,  r01);
        sg[t][3]  = pack2(-i01, -i01);
        sg[t][4]  = pack2(i00,  i00);
        sg[t][5]  = pack2(i01,  i01);
        sg[t][6]  = pack2(-r01, -r01);
        sg[t][7]  = 0;
        // mixed (vector-bit wire): lo half = pair-slot 0 math, hi half = slot 1
        sg[t][8]  = pack2(r00, -r01);
        sg[t][9]  = pack2(-i00, -i01);
        sg[t][10] = pack2(r01,  r00);
        sg[t][11] = pack2(-i01, i00);
        sg[t][12] = pack2(i00,  i01);
        sg[t][13] = pack2(i01, -i00);
    }

    // ---- init in registers: RX product state on |0..0> ----
    // Phase-A: y = (t<<5)|u. Unit k packs u=k (lo) and u=k+16 (hi).
    float tmag = 1.0f;
    #pragma unroll
    for (int j = 0; j < 9; j++) {
        float sv, cv;
        sincosf(0.5f * x[b * NQ + (8 - j)], &sv, &cv);
        tmag *= ((t >> j) & 1) ? sv : cv;
    }
    float su[5], cu[5];
    #pragma unroll
    for (int q = 0; q < 5; q++)
        sincosf(0.5f * x[b * NQ + (13 - q)], &su[q], &cu[q]);
    const int tp = __popc((unsigned)t);
    #pragma unroll
    for (int k = 0; k < HALF; k++) {
        float m = tmag;
        #pragma unroll
        for (int q = 0; q < 4; q++)
            m *= ((k >> q) & 1) ? su[q] : cu[q];
        float m0 = m * cu[4];                 // u bit4 = 0
        float m1 = m * su[4];                 // u bit4 = 1
        int k0 = (tp + __popc((unsigned)k)) & 3;
        int k1 = (k0 + 1) & 3;
        float re0 = (k0 == 0) ? m0 : ((k0 == 2) ? -m0 : 0.0f);
        float im0 = (k0 == 3) ? m0 : ((k0 == 1) ? -m0 : 0.0f);
        float re1 = (k1 == 0) ? m1 : ((k1 == 2) ? -m1 : 0.0f);
        float im1 = (k1 == 3) ? m1 : ((k1 == 1) ? -m1 : 0.0f);
        R[k] = pack2(re0, re1);
        I[k] = pack2(im0, im1);
    }
    __syncthreads();                          // sg[] ready

    for (int l = 0; l < NL; l++) {
        // ---- Phase A gather (layers 1,2): previous ring folded into addresses ----
        if (l > 0) {
            const int rr = l;
            unsigned Fcol[NQ];
            #pragma unroll
            for (int j = 0; j < NQ; j++) {
                unsigned z = 1u << j;
                for (int w = NQ - 1; w >= 0; w--) {
                    int bc = NQ - 1 - w;
                    int bt = NQ - 1 - ((w + rr) % NQ);
                    z ^= ((z >> bc) & 1u) << bt;
                }
                Fcol[j] = z;
            }
            unsigned Fb = 0;
            #pragma unroll
            for (int j = 0; j < 9; j++)
                if ((t >> j) & 1) Fb ^= Fcol[5 + j];
            const unsigned F4 = Fcol[4];
            #pragma unroll
            for (int k = 0; k < HALF; k++) {
                unsigned fy = Fb;
                if (k & 1) fy ^= Fcol[0];
                if (k & 2) fy ^= Fcol[1];
                if (k & 4) fy ^= Fcol[2];
                if (k & 8) fy ^= Fcol[3];
                float2 a = s[swz(fy)];
                float2 c = s[swz(fy ^ F4)];
                R[k] = pack2(a.x, c.x);
                I[k] = pack2(a.y, c.y);
            }
        }

        // ---- Phase A gates ----
        // wires 13-10 on u bits 0-3 (vectorized)
        #pragma unroll
        for (int q = 0; q < 4; q++) {
            const u64* g = sg[l * NQ + (13 - q)];
            #pragma unroll
            for (int k = 0; k < HALF; k++)
                if (!(k & (1 << q)))
                    apply2v(g, R[k], I[k], R[k | (1 << q)], I[k | (1 << q)]);
        }
        // wire 9 on u bit 4 (vector bit): intra-register, mixed consts
        {
            const u64* g = sg[l * NQ + 9];
            #pragma unroll
            for (int k = 0; k < HALF; k++) {
                u64 br0 = blo(R[k]), bi0 = blo(I[k]);
                u64 br1 = bhi(R[k]), bi1 = bhi(I[k]);
                u64 nr = mul2(br0, g[8]);  nr = fma2(bi0, g[9],  nr); nr = fma2(br1, g[10], nr); nr = fma2(bi1, g[11], nr);
                u64 ni = mul2(br0, g[12]); ni = fma2(bi0, g[8],  ni); ni = fma2(br1, g[13], ni); ni = fma2(bi1, g[10], ni);
                R[k] = nr; I[k] = ni;
            }
        }
        // wires 8-5 on lane bits 0-3 (vectorized, lane-selected consts)
        #pragma unroll
        for (int ql = 0; ql < 4; ql++) {
            const u64* g = sg[l * NQ + (8 - ql)];
            int bit = (lane >> ql) & 1;
            u64 Arr = g[0];
            u64 Ari = bit ? g[4] : g[1];
            u64 Air = bit ? g[1] : g[4];
            u64 Brr = bit ? g[6] : g[2];
            u64 Bri = g[3];
            u64 Bir = g[5];
            #pragma unroll
            for (int k = 0; k < HALF; k++) {
                u64 oR = __shfl_xor_sync(0xffffffffu, R[k], 1 << ql);
                u64 oI = __shfl_xor_sync(0xffffffffu, I[k], 1 << ql);
                u64 nr = mul2(R[k], Arr); nr = fma2(I[k], Ari, nr); nr = fma2(oR, Brr, nr); nr = fma2(oI, Bri, nr);
                u64 ni = mul2(R[k], Air); ni = fma2(I[k], Arr, ni); ni = fma2(oR, Bir, ni); ni = fma2(oI, Brr, ni);
                R[k] = nr; I[k] = ni;
            }
        }

        __syncthreads();                      // all phase-A gathers done
        #pragma unroll
        for (int k = 0; k < HALF; k++) {      // store scalar contiguous layout
            float r0, r1, i0, i1;
            unpack2(R[k], r0, r1); unpack2(I[k], i0, i1);
            unsigned y0 = ((unsigned)t << 5) | (unsigned)k;
            s[swz(y0)]      = make_float2(r0, i0);
            s[swz(y0 | 16)] = make_float2(r1, i1);
        }
        __syncthreads();                      // stores visible

        // ---- Phase B: y = (u<<9)|t, unit k packs u=k (lo) and u=k+16 (hi) ----
        #pragma unroll
        for (int k = 0; k < HALF; k++) {
            unsigned y0 = ((unsigned)k << 9) | (unsigned)t;
            float2 a = s[swz(y0)];
            float2 c = s[swz(y0 | (1u << 13))];
            R[k] = pack2(a.x, c.x);
            I[k] = pack2(a.y, c.y);
        }
        // wires 4-1 on u bits 0-3 (vectorized)
        #pragma unroll
        for (int q = 0; q < 4; q++) {
            const u64* g = sg[l * NQ + (4 - q)];
            #pragma unroll
            for (int k = 0; k < HALF; k++)
                if (!(k & (1 << q)))
                    apply2v(g, R[k], I[k], R[k | (1 << q)], I[k | (1 << q)]);
        }
        // wire 0 on u bit 4 (vector bit)
        {
            const u64* g = sg[l * NQ + 0];
            #pragma unroll
            for (int k = 0; k < HALF; k++) {
                u64 br0 = blo(R[k]), bi0 = blo(I[k]);
                u64 br1 = bhi(R[k]), bi1 = bhi(I[k]);
                u64 nr = mul2(br0, g[8]);  nr = fma2(bi0, g[9],  nr); nr = fma2(br1, g[10], nr); nr = fma2(bi1, g[11], nr);
                u64 ni = mul2(br0, g[12]); ni = fma2(bi0, g[8],  ni); ni = fma2(br1, g[13], ni); ni = fma2(bi1, g[10], ni);
                R[k] = nr; I[k] = ni;
            }
        }

        if (l < NL - 1) {
            __syncthreads();                  // all phase-B loads done
            #pragma unroll
            for (int k = 0; k < HALF; k++) {
                float r0, r1, i0, i1;
                unpack2(R[k], r0, r1); unpack2(I[k], i0, i1);
                unsigned y0 = ((unsigned)k << 9) | (unsigned)t;
                s[swz(y0)]              = make_float2(r0, i0);
                s[swz(y0 | (1u << 13))] = make_float2(r1, i1);
            }
            __syncthreads();                  // stores visible for next A-gather
        }
    }

    // ---- last CNOT ring (r = NL) folded into expval signs (validated) ----
    unsigned Ar[NQ];
    #pragma unroll
    for (int i = 0; i < NQ; i++) Ar[i] = 1u << i;
    {
        const int rr = NL;
        #pragma unroll
        for (int w = 0; w < NQ; w++) {
            int bc = NQ - 1 - w;
            int bt = NQ - 1 - ((w + rr) % NQ);
            Ar[bt] ^= Ar[bc];
        }
    }
    float    wl[NQ];
    unsigned rf[NQ];
    #pragma unroll
    for (int w = 0; w < NQ; w++) { wl[w] = wlin[w]; rf[w] = Ar[NQ - 1 - w]; }

    float acc = 0.0f;
    #pragma unroll
    for (int k = 0; k < HALF; k++) {
        u64 P = fma2(R[k], R[k], mul2(I[k], I[k]));   // packed |amp|^2
        float p0, p1;
        unpack2(P, p0, p1);
        unsigned y0 = ((unsigned)k << 9) | (unsigned)t;
        unsigned y1 = y0 | (1u << 13);
        float z0 = 0.0f, z1 = 0.0f;
        #pragma unroll
        for (int w = 0; w < NQ; w++) {
            z0 += ((__popc(rf[w] & y0) & 1) ? -wl[w] : wl[w]);
            z1 += ((__popc(rf[w] & y1) & 1) ? -wl[w] : wl[w]);
        }
        acc += p0 * z0 + p1 * z1;
    }
    #pragma unroll
    for (int off = 16; off; off >>= 1)
        acc += __shfl_down_sync(0xffffffffu, acc, off);
    if (lane == 0) red[t >> 5] = acc;
    __syncthreads();
    if (t == 0) {
        float tot = 0.0f;
        #pragma unroll
        for (int q = 0; q < TPB / 32; q++) tot += red[q];
        out[b] = tot + blin[0];
    }
}

extern "C" void kernel_launch(void* const* d_in, const int* in_sizes, int n_in,
                              void* d_out, int out_size)
{
    // Bind inputs by element count (robust to metadata ordering):
    //   x: 128*14 = 1792, q_weights: 3*14*3 = 126, w_lin: 14, b_lin: 1
    const float* x    = nullptr;
    const float* qw   = nullptr;
    const float* wlin = nullptr;
    const float* blin = nullptr;
    for (int i = 0; i < n_in; i++) {
        switch (in_sizes[i]) {
            case 1792: x    = (const float*)d_in[i]; break;
            case 126:  qw   = (const float*)d_in[i]; break;
            case 14:   wlin = (const float*)d_in[i]; break;
            case 1:    blin = (const float*)d_in[i]; break;
            default: break;
        }
    }
    float* out = (float*)d_out;                  // (128, 1)

    cudaFuncSetAttribute(qsim_kernel,
                         cudaFuncAttributeMaxDynamicSharedMemorySize,
                         SMEM_BYTES);

    qsim_kernel<<<128, TPB, SMEM_BYTES>>>(x, qw, wlin, blin, out);
}